// round 5
// baseline (speedup 1.0000x reference)
#include <cuda_runtime.h>
#include <cuda_bf16.h>
#include <math.h>

// SymLoss: B=32, C=4, N=16384, RES=32
// inputs: y_pred (32,4,4) f32, points (32,16384,3) f32,
//         voxel_grid (unused), voxel_grid_cp (32,32,32,32,3) f32
// output: 1 f32

#define B_   32
#define C_   4
#define N_   16384
#define RES_ 32
#define VOX_ (RES_ * RES_ * RES_)   // 32768
#define CHUNKS_ 32                  // blocks per batch in reflect kernel
#define TPB_ 256
#define PTS_PER_THREAD_ 2           // 32*256*2 = 16384
#define NBLK_ (B_ * CHUNKS_)        // 1024
#define REG_COEF_ 25.0f

__device__ float        g_planes[B_][C_][4];   // nhat.x, nhat.y, nhat.z, d
__device__ float        g_partial[NBLK_];
__device__ float        g_reg;
__device__ float4       g_grid4[B_ * VOX_];    // 16 MB padded copy of voxel_grid_cp
__device__ unsigned int g_count;               // zero-init; atomicInc wrap self-resets

// ---------------------------------------------------------------------------
// Kernel 1: pad voxel_grid_cp -> float4 array, AND (block 0, warp 0) compute
// normalized planes + Gram regularizer.
// ---------------------------------------------------------------------------
__global__ __launch_bounds__(256) void prep_kernel(
    const float* __restrict__ cp,
    const float* __restrict__ y_pred)
{
    int i = blockIdx.x * blockDim.x + threadIdx.x;   // 0 .. B_*VOX_-1
    const float* s = cp + (size_t)i * 3;
    float4 v;
    v.x = __ldg(s + 0);
    v.y = __ldg(s + 1);
    v.z = __ldg(s + 2);
    v.w = 0.0f;
    g_grid4[i] = v;

    if (blockIdx.x == 0 && threadIdx.x < B_) {
        int b = threadIdx.x;                         // one thread per batch
        float nx[C_], ny[C_], nz[C_];
        #pragma unroll
        for (int c = 0; c < C_; c++) {
            float x = y_pred[b * 16 + c * 4 + 0];
            float y = y_pred[b * 16 + c * 4 + 1];
            float z = y_pred[b * 16 + c * 4 + 2];
            float d = y_pred[b * 16 + c * 4 + 3];
            float inv = 1.0f / sqrtf(x * x + y * y + z * z);
            nx[c] = x * inv; ny[c] = y * inv; nz[c] = z * inv;
            g_planes[b][c][0] = nx[c];
            g_planes[b][c][1] = ny[c];
            g_planes[b][c][2] = nz[c];
            g_planes[b][c][3] = d;
        }
        // Frobenius norm of (nhat nhat^T - I)
        float acc = 0.0f;
        #pragma unroll
        for (int c = 0; c < C_; c++) {
            #pragma unroll
            for (int e = 0; e < C_; e++) {
                float g = nx[c] * nx[e] + ny[c] * ny[e] + nz[c] * nz[e]
                          - (c == e ? 1.0f : 0.0f);
                acc += g * g;
            }
        }
        float reg_b = sqrtf(acc);
        #pragma unroll
        for (int off = 16; off > 0; off >>= 1)
            reg_b += __shfl_down_sync(0xFFFFFFFFu, reg_b, off);
        if (b == 0)
            g_reg = REG_COEF_ * (reg_b / (float)B_);
    }
}

// ---------------------------------------------------------------------------
// Kernel 2: reflection + float4 voxel gather + norm; last block finalizes.
// Gathers staged per point (4 independent LDG.128 per stage) to keep
// register pressure ~60 -> 4 blocks/SM.
// ---------------------------------------------------------------------------
__global__ __launch_bounds__(TPB_) void reflect_kernel(
    const float* __restrict__ points,
    float* __restrict__ out)
{
    __shared__ float s_plane[C_][4];
    __shared__ float s_red[TPB_ / 32];
    __shared__ int   s_last;

    const int b     = blockIdx.x / CHUNKS_;
    const int chunk = blockIdx.x % CHUNKS_;
    const int tid   = threadIdx.x;

    if (tid < C_ * 4)
        ((float*)s_plane)[tid] = ((const float*)g_planes[b])[tid];
    __syncthreads();

    const float*  pts = points + ((size_t)b * N_ + (size_t)chunk * (N_ / CHUNKS_)) * 3;
    const float4* g4  = g_grid4 + (size_t)b * VOX_;

    float pnx[C_], pny[C_], pnz[C_], pd[C_];
    #pragma unroll
    for (int c = 0; c < C_; c++) {
        pnx[c] = s_plane[c][0];
        pny[c] = s_plane[c][1];
        pnz[c] = s_plane[c][2];
        pd[c]  = s_plane[c][3];
    }

    // hoist point loads (coalesced, front-batched)
    float px[PTS_PER_THREAD_], py[PTS_PER_THREAD_], pz[PTS_PER_THREAD_];
    #pragma unroll
    for (int i = 0; i < PTS_PER_THREAD_; i++) {
        const float* p = pts + (size_t)(tid + i * TPB_) * 3;
        px[i] = __ldg(p + 0);
        py[i] = __ldg(p + 1);
        pz[i] = __ldg(p + 2);
    }

    float acc = 0.0f;

    #pragma unroll
    for (int i = 0; i < PTS_PER_THREAD_; i++) {
        // reflections + indices for this point: 4 independent gathers
        float rx[C_], ry[C_], rz[C_];
        int   idx[C_];
        #pragma unroll
        for (int c = 0; c < C_; c++) {
            float dist = fmaf(px[i], pnx[c],
                         fmaf(py[i], pny[c],
                         fmaf(pz[i], pnz[c], pd[c])));
            float t = 2.0f * dist;
            rx[c] = fmaf(-t, pnx[c], px[i]);
            ry[c] = fmaf(-t, pny[c], py[i]);
            rz[c] = fmaf(-t, pnz[c], pz[i]);

            float fx = fminf(fmaxf(floorf(rx[c] * (float)RES_), 0.0f), (float)(RES_ - 1));
            float fy = fminf(fmaxf(floorf(ry[c] * (float)RES_), 0.0f), (float)(RES_ - 1));
            float fz = fminf(fmaxf(floorf(rz[c] * (float)RES_), 0.0f), (float)(RES_ - 1));
            idx[c] = (((int)fx * RES_ + (int)fy) * RES_ + (int)fz);
        }

        float4 cpv[C_];
        #pragma unroll
        for (int c = 0; c < C_; c++)
            cpv[c] = __ldg(g4 + idx[c]);

        #pragma unroll
        for (int c = 0; c < C_; c++) {
            float dx = rx[c] - cpv[c].x;
            float dy = ry[c] - cpv[c].y;
            float dz = rz[c] - cpv[c].z;
            acc += sqrtf(fmaf(dx, dx, fmaf(dy, dy, dz * dz)));
        }
    }

    // deterministic block tree reduction
    #pragma unroll
    for (int off = 16; off > 0; off >>= 1)
        acc += __shfl_down_sync(0xFFFFFFFFu, acc, off);
    if ((tid & 31) == 0)
        s_red[tid >> 5] = acc;
    __syncthreads();
    if (tid < 32) {
        float v = (tid < TPB_ / 32) ? s_red[tid] : 0.0f;
        #pragma unroll
        for (int off = 4; off > 0; off >>= 1)
            v += __shfl_down_sync(0xFFFFFFFFu, v, off);
        if (tid == 0) {
            g_partial[blockIdx.x] = v;
            __threadfence();
            // atomicInc wraps to 0 after NBLK_-1 -> self-resetting across replays
            unsigned int prev = atomicInc(&g_count, NBLK_ - 1);
            s_last = (prev == NBLK_ - 1) ? 1 : 0;
        }
    }
    __syncthreads();

    // last block: deterministic final reduction of all 1024 partials
    if (s_last) {
        float v = 0.0f;
        #pragma unroll
        for (int j = 0; j < NBLK_ / TPB_; j++)      // 4 partials per thread, fixed order
            v += g_partial[tid + j * TPB_];
        #pragma unroll
        for (int off = 16; off > 0; off >>= 1)
            v += __shfl_down_sync(0xFFFFFFFFu, v, off);
        if ((tid & 31) == 0)
            s_red[tid >> 5] = v;
        __syncthreads();
        if (tid < 32) {
            float w = (tid < TPB_ / 32) ? s_red[tid] : 0.0f;
            #pragma unroll
            for (int off = 4; off > 0; off >>= 1)
                w += __shfl_down_sync(0xFFFFFFFFu, w, off);
            if (tid == 0)
                out[0] = w * (1.0f / (float)N_) + g_reg;
        }
    }
}

// ---------------------------------------------------------------------------
extern "C" void kernel_launch(void* const* d_in, const int* in_sizes, int n_in,
                              void* d_out, int out_size)
{
    const float* y_pred  = (const float*)d_in[0];
    const float* points  = (const float*)d_in[1];
    // d_in[2] = voxel_grid is unused by the reference math
    const float* grid_cp = (const float*)d_in[3];
    float* out = (float*)d_out;

    prep_kernel<<<(B_ * VOX_) / 256, 256>>>(grid_cp, y_pred);
    reflect_kernel<<<NBLK_, TPB_>>>(points, out);
}

// round 9
// speedup vs baseline: 1.0033x; 1.0033x over previous
#include <cuda_runtime.h>
#include <cuda_bf16.h>
#include <math.h>

// SymLoss: B=32, C=4, N=16384, RES=32
// inputs: y_pred (32,4,4) f32, points (32,16384,3) f32,
//         voxel_grid (unused), voxel_grid_cp (32,32,32,32,3) f32
// output: 1 f32

#define B_   32
#define C_   4
#define N_   16384
#define RES_ 32
#define VOX_ (RES_ * RES_ * RES_)   // 32768
#define CHUNKS_ 64                  // blocks per batch in reflect kernel
#define TPB_ 256
#define NBLK_ (B_ * CHUNKS_)        // 2048 ; 256 points per block, 1 pt/thread
#define REG_COEF_ 25.0f

#define PREP_VOX_PER_BLK_ 1024      // 256 threads x 4 voxels
#define PREP_NBLK_ ((B_ * VOX_) / PREP_VOX_PER_BLK_)   // 1024

__device__ float        g_planes[B_][C_][4];   // nhat.x, nhat.y, nhat.z, d
__device__ float        g_partial[NBLK_];
__device__ float        g_reg;
__device__ float4       g_grid4[B_ * VOX_];    // 16 MB padded copy of voxel_grid_cp
__device__ unsigned int g_count;               // zero-init; atomicInc wrap self-resets

// ---------------------------------------------------------------------------
// Kernel 1: pad voxel_grid_cp -> float4 (fully coalesced via smem staging),
// AND (block 0, threads<32) compute normalized planes + Gram regularizer.
// ---------------------------------------------------------------------------
__global__ __launch_bounds__(TPB_) void prep_kernel(
    const float4* __restrict__ cp4,      // voxel_grid_cp viewed as float4 stream
    const float*  __restrict__ y_pred)
{
    __shared__ float s_stage[PREP_VOX_PER_BLK_ * 3];   // 12 KB

    const int tid   = threadIdx.x;
    const int vbase = blockIdx.x * PREP_VOX_PER_BLK_;

    // 3 perfectly coalesced float4 loads per thread (768 float4 = 3072 floats)
    const float4* src = cp4 + (size_t)vbase * 3 / 4;   // vbase*3 floats /4
    float4* s4 = (float4*)s_stage;
    #pragma unroll
    for (int k = 0; k < 3; k++)
        s4[tid + k * TPB_] = src[tid + k * TPB_];
    __syncthreads();

    // emit 4 padded voxels per thread, coalesced float4 stores, L2-resident hint
    #pragma unroll
    for (int k = 0; k < 4; k++) {
        int vloc = tid + k * TPB_;
        float4 v;
        v.x = s_stage[vloc * 3 + 0];
        v.y = s_stage[vloc * 3 + 1];
        v.z = s_stage[vloc * 3 + 2];
        v.w = 0.0f;
        __stcg(&g_grid4[vbase + vloc], v);
    }

    if (blockIdx.x == 0 && tid < B_) {
        int b = tid;                                   // one thread per batch
        float nx[C_], ny[C_], nz[C_];
        #pragma unroll
        for (int c = 0; c < C_; c++) {
            float x = y_pred[b * 16 + c * 4 + 0];
            float y = y_pred[b * 16 + c * 4 + 1];
            float z = y_pred[b * 16 + c * 4 + 2];
            float d = y_pred[b * 16 + c * 4 + 3];
            float inv = 1.0f / sqrtf(x * x + y * y + z * z);
            nx[c] = x * inv; ny[c] = y * inv; nz[c] = z * inv;
            g_planes[b][c][0] = nx[c];
            g_planes[b][c][1] = ny[c];
            g_planes[b][c][2] = nz[c];
            g_planes[b][c][3] = d;
        }
        float acc = 0.0f;
        #pragma unroll
        for (int c = 0; c < C_; c++) {
            #pragma unroll
            for (int e = 0; e < C_; e++) {
                float g = nx[c] * nx[e] + ny[c] * ny[e] + nz[c] * nz[e]
                          - (c == e ? 1.0f : 0.0f);
                acc += g * g;
            }
        }
        float reg_b = sqrtf(acc);
        #pragma unroll
        for (int off = 16; off > 0; off >>= 1)
            reg_b += __shfl_down_sync(0xFFFFFFFFu, reg_b, off);
        if (b == 0)
            g_reg = REG_COEF_ * (reg_b / (float)B_);
    }
}

// ---------------------------------------------------------------------------
// Kernel 2: reflection + float4 voxel gather + norm; last block finalizes.
// 1 point/thread, low regs -> 5 blocks/SM for latency hiding (spill-safe cap).
// ---------------------------------------------------------------------------
__global__ __launch_bounds__(TPB_, 5) void reflect_kernel(
    const float* __restrict__ points,
    float* __restrict__ out)
{
    __shared__ float s_plane[C_][4];
    __shared__ float s_pts[TPB_ * 3];
    __shared__ float s_red[TPB_ / 32];
    __shared__ int   s_last;

    const int b     = blockIdx.x / CHUNKS_;
    const int chunk = blockIdx.x % CHUNKS_;
    const int tid   = threadIdx.x;

    if (tid < C_ * 4)
        ((float*)s_plane)[tid] = ((const float*)g_planes[b])[tid];

    // coalesced stage of this block's 256 points (768 floats = 192 float4)
    const float4* pts4 = (const float4*)(points + ((size_t)b * N_ + (size_t)chunk * TPB_) * 3);
    if (tid < 192)
        ((float4*)s_pts)[tid] = pts4[tid];
    __syncthreads();

    const float4* g4 = g_grid4 + (size_t)b * VOX_;

    const float px = s_pts[tid * 3 + 0];
    const float py = s_pts[tid * 3 + 1];
    const float pz = s_pts[tid * 3 + 2];

    // reflections + gather indices: 4 independent LDG.128
    float rx[C_], ry[C_], rz[C_];
    int   idx[C_];
    #pragma unroll
    for (int c = 0; c < C_; c++) {
        const float nx = s_plane[c][0];
        const float ny = s_plane[c][1];
        const float nz = s_plane[c][2];
        const float d  = s_plane[c][3];
        float dist = fmaf(px, nx, fmaf(py, ny, fmaf(pz, nz, d)));
        float t = 2.0f * dist;
        rx[c] = fmaf(-t, nx, px);
        ry[c] = fmaf(-t, ny, py);
        rz[c] = fmaf(-t, nz, pz);

        int ix = min(max(__float2int_rd(rx[c] * (float)RES_), 0), RES_ - 1);
        int iy = min(max(__float2int_rd(ry[c] * (float)RES_), 0), RES_ - 1);
        int iz = min(max(__float2int_rd(rz[c] * (float)RES_), 0), RES_ - 1);
        idx[c] = (ix * RES_ + iy) * RES_ + iz;
    }

    float4 cpv[C_];
    #pragma unroll
    for (int c = 0; c < C_; c++)
        cpv[c] = __ldg(g4 + idx[c]);

    float acc = 0.0f;
    #pragma unroll
    for (int c = 0; c < C_; c++) {
        float dx = rx[c] - cpv[c].x;
        float dy = ry[c] - cpv[c].y;
        float dz = rz[c] - cpv[c].z;
        acc += sqrtf(fmaf(dx, dx, fmaf(dy, dy, dz * dz)));
    }

    // deterministic block tree reduction
    #pragma unroll
    for (int off = 16; off > 0; off >>= 1)
        acc += __shfl_down_sync(0xFFFFFFFFu, acc, off);
    if ((tid & 31) == 0)
        s_red[tid >> 5] = acc;
    __syncthreads();
    if (tid < 32) {
        float v = (tid < TPB_ / 32) ? s_red[tid] : 0.0f;
        #pragma unroll
        for (int off = 4; off > 0; off >>= 1)
            v += __shfl_down_sync(0xFFFFFFFFu, v, off);
        if (tid == 0) {
            g_partial[blockIdx.x] = v;
            __threadfence();
            // atomicInc wraps to 0 after NBLK_-1 -> self-resetting across replays
            unsigned int prev = atomicInc(&g_count, NBLK_ - 1);
            s_last = (prev == NBLK_ - 1) ? 1 : 0;
        }
    }
    __syncthreads();

    // last block: deterministic final reduction of all 2048 partials
    if (s_last) {
        float v = 0.0f;
        #pragma unroll
        for (int j = 0; j < NBLK_ / TPB_; j++)      // 8 partials per thread, fixed order
            v += g_partial[tid + j * TPB_];
        #pragma unroll
        for (int off = 16; off > 0; off >>= 1)
            v += __shfl_down_sync(0xFFFFFFFFu, v, off);
        if ((tid & 31) == 0)
            s_red[tid >> 5] = v;
        __syncthreads();
        if (tid < 32) {
            float w = (tid < TPB_ / 32) ? s_red[tid] : 0.0f;
            #pragma unroll
            for (int off = 4; off > 0; off >>= 1)
                w += __shfl_down_sync(0xFFFFFFFFu, w, off);
            if (tid == 0)
                out[0] = w * (1.0f / (float)N_) + g_reg;
        }
    }
}

// ---------------------------------------------------------------------------
extern "C" void kernel_launch(void* const* d_in, const int* in_sizes, int n_in,
                              void* d_out, int out_size)
{
    const float*  y_pred  = (const float*)d_in[0];
    const float*  points  = (const float*)d_in[1];
    // d_in[2] = voxel_grid is unused by the reference math
    const float4* grid_cp = (const float4*)d_in[3];   // 12MB, float4-viewable (divisible)
    float* out = (float*)d_out;

    prep_kernel<<<PREP_NBLK_, TPB_>>>(grid_cp, y_pred);
    reflect_kernel<<<NBLK_, TPB_>>>(points, out);
}